// round 1
// baseline (speedup 1.0000x reference)
#include <cuda_runtime.h>

#define Nn   100000
#define Ee   3200000
#define IND  128
#define HIDD 64
#define HH   4
#define OF   256      // HH*HIDD
#define BN   32       // nodes per MLP tile
#define RELN 50
#define LL   3

// ---------------- scratch (device globals; no allocation allowed) ----------
__device__ __align__(16) float g_h[Nn * HH];        // per-node per-head state
__device__ __align__(16) float g_acc[Nn * 8];       // [num0..3 | S0..3] per node
__device__ __align__(16) float g_erel[RELN * HH];   // exp(leaky_relu(rel @ Wp))

// ---------------- per-layer relation attention table -----------------------
__global__ void erel_kernel(const float* __restrict__ rel_emb,
                            const float* __restrict__ W_pred, int layer) {
    int t = threadIdx.x;
    if (t < RELN * HH) {
        int r = t >> 2, h = t & 3;
        const float* wp = W_pred + layer * 16 * HH;   // (16,4) slice
        float s = 0.f;
#pragma unroll
        for (int p = 0; p < 16; p++) s = fmaf(rel_emb[r * 16 + p], wp[p * HH + h], s);
        s = (s > 0.f) ? s : 0.2f * s;                 // leaky_relu(0.2)
        g_erel[t] = expf(s);
    }
}

__global__ void zero_kernel() {
    int i = blockIdx.x * blockDim.x + threadIdx.x;
    if (i < Nn * 8) g_acc[i] = 0.f;
}

// ---------------- fused multi-head scoring MLP ------------------------------
// h[n][k] = sum_j W2[k][j]*relu(sum_i W1[k][j][i]*x[n][i] + b1[k][j]) + b2[k]
__global__ __launch_bounds__(256, 1)
void mlp_kernel(const float* __restrict__ X,  const float* __restrict__ W1,
                const float* __restrict__ b1, const float* __restrict__ W2,
                const float* __restrict__ b2) {
    extern __shared__ float sm[];
    float* W1s = sm;                    // OF rows x stride 132 (pad: no conflicts)
    float* Xs  = sm + OF * 132;         // BN rows x stride 132
    float* W2s = Xs + BN * 132;         // OF
    float* b1s = W2s + OF;              // OF
    __shared__ float wsum[8][BN];
    __shared__ float b2s[HH];

    int tid = threadIdx.x;
    int warp = tid >> 5, lane = tid & 31;

    // stage all weights in shared memory once per block
    for (int idx4 = tid; idx4 < OF * 32; idx4 += 256) {
        int t = idx4 >> 5, i4 = idx4 & 31;
        float4 v = ((const float4*)W1)[idx4];         // W1 flat (OF,128)
        *(float4*)&W1s[t * 132 + i4 * 4] = v;
    }
    if (tid < OF) { W2s[tid] = W2[tid]; b1s[tid] = b1[tid]; }
    if (tid < HH) b2s[tid] = b2[tid];
    __syncthreads();

    float w2v = W2s[tid];
    float b1v = b1s[tid];

    for (int tile = blockIdx.x; tile < Nn / BN; tile += gridDim.x) {
        __syncthreads();   // protect Xs / wsum from previous-iteration readers
        for (int idx = tid; idx < BN * 32; idx += 256) {
            int n = idx >> 5, i4 = idx & 31;
            float4 v = ((const float4*)X)[(tile * BN + n) * 32 + i4];
            *(float4*)&Xs[n * 132 + i4 * 4] = v;
        }
        __syncthreads();

        float acc[BN];
#pragma unroll
        for (int n = 0; n < BN; n++) acc[n] = b1v;

        for (int i4 = 0; i4 < 32; i4++) {
            float4 w = *(const float4*)&W1s[tid * 132 + i4 * 4];
#pragma unroll
            for (int n = 0; n < BN; n++) {
                float4 x = *(const float4*)&Xs[n * 132 + i4 * 4];  // smem broadcast
                acc[n] = fmaf(w.x, x.x, acc[n]);
                acc[n] = fmaf(w.y, x.y, acc[n]);
                acc[n] = fmaf(w.z, x.z, acc[n]);
                acc[n] = fmaf(w.w, x.w, acc[n]);
            }
        }

        // reduce 64 hidden units per head: warp shuffle + 2-warp combine
#pragma unroll
        for (int n = 0; n < BN; n++) {
            float v = w2v * fmaxf(acc[n], 0.f);
#pragma unroll
            for (int o = 16; o; o >>= 1) v += __shfl_down_sync(0xffffffffu, v, o);
            if (lane == 0) wsum[warp][n] = v;
        }
        __syncthreads();
        if (tid < BN * HH) {
            int n = tid >> 2, k = tid & 3;
            g_h[(tile * BN + n) * HH + k] = wsum[2 * k][n] + wsum[2 * k + 1][n] + b2s[k];
        }
    }
}

// ---------------- edge aggregation pass -------------------------------------
__global__ __launch_bounds__(256)
void edge_kernel(const int* __restrict__ et, const int* __restrict__ srcv,
                 const int* __restrict__ dstv) {
    __shared__ float4 er[RELN];
    if (threadIdx.x < RELN) er[threadIdx.x] = ((const float4*)g_erel)[threadIdx.x];
    __syncthreads();
    int e = blockIdx.x * 256 + threadIdx.x;
    if (e >= Ee) return;
    int t = et[e], s = srcv[e], d = dstv[e];
    float4 w  = er[t];
    float4 hs = ((const float4*)g_h)[s];
    float* base = g_acc + (size_t)d * 8;
    asm volatile("red.global.add.v4.f32 [%0], {%1,%2,%3,%4};"
                 :: "l"(base), "f"(w.x * hs.x), "f"(w.y * hs.y),
                    "f"(w.z * hs.z), "f"(w.w * hs.w) : "memory");
    asm volatile("red.global.add.v4.f32 [%0], {%1,%2,%3,%4};"
                 :: "l"(base + 4), "f"(w.x), "f"(w.y), "f"(w.z), "f"(w.w) : "memory");
}

// ---------------- per-node softmax-normalize + relu (+ head mean) -----------
__global__ void update_kernel(int last) {
    int n = blockIdx.x * blockDim.x + threadIdx.x;
    if (n >= Nn) return;
    float4 num = ((const float4*)g_acc)[n * 2];
    float4 S   = ((const float4*)g_acc)[n * 2 + 1];
    float h0 = (S.x > 0.f) ? fmaxf(num.x / S.x, 0.f) : 0.f;
    float h1 = (S.y > 0.f) ? fmaxf(num.y / S.y, 0.f) : 0.f;
    float h2 = (S.z > 0.f) ? fmaxf(num.z / S.z, 0.f) : 0.f;
    float h3 = (S.w > 0.f) ? fmaxf(num.w / S.w, 0.f) : 0.f;
    if (!last) {
        float m = 0.25f * (h0 + h1 + h2 + h3);
        h0 = h1 = h2 = h3 = m;
    }
    ((float4*)g_h)[n] = make_float4(h0, h1, h2, h3);
}

// ---------------- final centrality scaling -----------------------------------
__global__ void final_kernel(const float* __restrict__ cent,
                             const float* __restrict__ gamma,
                             const float* __restrict__ beta,
                             float* __restrict__ out) {
    int n = blockIdx.x * blockDim.x + threadIdx.x;
    if (n >= Nn) return;
    float c = cent[n];
    float4 h = ((const float4*)g_h)[n];
    float v = fmaf(c, gamma[0], beta[0]) * h.x
            + fmaf(c, gamma[1], beta[1]) * h.y
            + fmaf(c, gamma[2], beta[2]) * h.z
            + fmaf(c, gamma[3], beta[3]) * h.w;
    v *= 0.25f;
    out[n] = (v > 0.f) ? v : 0.01f * v;
}

// ---------------- launch ------------------------------------------------------
extern "C" void kernel_launch(void* const* d_in, const int* in_sizes, int n_in,
                              void* d_out, int out_size) {
    const float* X       = (const float*)d_in[0];
    const float* cent    = (const float*)d_in[1];
    const float* W1      = (const float*)d_in[2];
    const float* b1      = (const float*)d_in[3];
    const float* W2      = (const float*)d_in[4];
    const float* b2      = (const float*)d_in[5];
    const float* rel_emb = (const float*)d_in[6];
    const float* W_pred  = (const float*)d_in[7];
    const float* gamma   = (const float*)d_in[8];
    const float* beta    = (const float*)d_in[9];
    const int*   et      = (const int*)d_in[10];
    const int*   src     = (const int*)d_in[11];
    const int*   dst     = (const int*)d_in[12];
    float* out = (float*)d_out;

    const int dyn_smem = (OF * 132 + BN * 132 + OF + OF) * (int)sizeof(float);
    cudaFuncSetAttribute(mlp_kernel, cudaFuncAttributeMaxDynamicSharedMemorySize,
                         dyn_smem);

    mlp_kernel<<<148, 256, dyn_smem>>>(X, W1, b1, W2, b2);
    for (int l = 0; l < LL; l++) {
        erel_kernel<<<1, 256>>>(rel_emb, W_pred, l);
        zero_kernel<<<(Nn * 8 + 255) / 256, 256>>>();
        edge_kernel<<<(Ee + 255) / 256, 256>>>(et, src, dst);
        update_kernel<<<(Nn + 255) / 256, 256>>>(l == LL - 1 ? 1 : 0);
    }
    final_kernel<<<(Nn + 255) / 256, 256>>>(cent, gamma, beta, out);
}